// round 3
// baseline (speedup 1.0000x reference)
#include <cuda_runtime.h>
#include <cuda_fp16.h>
#include <cstdint>

// ---------------------------------------------------------------------------
// CELP edge-MLP:
//   x_ij = x[e0]*x[e1]                       [E,128]
//   z1 = x_ij@w1+b1 ; h1 = relu(BN1(z1))
//   z2 = h1@w2+b2   ; h2 = relu(BN2(z2))
//   out = h2@wc+bc                           [E,1]
// BN is training-mode over the E dim -> 2 global stat reductions.
// 3 GEMM passes, fp16 intermediate storage, stats via frag-level shfl
// reduce + smem + global atomics, analytic pad-row correction.
// Edge index dtype (int32 vs int64) detected at runtime (device flag).
// ---------------------------------------------------------------------------

#define EMAX 1000000
#define MT 128          // rows (edges) per block tile
#define SROW 136        // smem row stride in halfs (8-half pad -> conflict free)

static __device__ __half g_z1[(size_t)EMAX * 128];
static __device__ __half g_z2[(size_t)EMAX * 128];
static __device__ float g_s[2][128];
static __device__ float g_q[2][128];
static __device__ float g_scale[2][128];
static __device__ float g_shift[2][128];
static __device__ int g_is64;

__global__ void k_detect(const void* edges) {
    // int64 data: all sampled values < 2^31 (hi words zero).
    // int32 data: reading as int64 pairs two indices -> huge values.
    const long long* e64 = (const long long*)edges;
    int is64 = 1;
    for (int i = 0; i < 8; i++) {
        long long v = e64[i];
        if (v < 0 || v >= (1LL << 31)) is64 = 0;
    }
    g_is64 = is64;
    int t = threadIdx.x;
    if (t < 128) {
        g_s[0][t] = 0.f; g_s[1][t] = 0.f;
        g_q[0][t] = 0.f; g_q[1][t] = 0.f;
    }
}

__device__ __forceinline__ void mma16816(float* c, const uint32_t* a,
                                         uint32_t b0, uint32_t b1) {
    asm volatile(
        "mma.sync.aligned.m16n8k16.row.col.f32.f16.f16.f32 "
        "{%0,%1,%2,%3}, {%4,%5,%6,%7}, {%8,%9}, {%0,%1,%2,%3};\n"
        : "+f"(c[0]), "+f"(c[1]), "+f"(c[2]), "+f"(c[3])
        : "r"(a[0]), "r"(a[1]), "r"(a[2]), "r"(a[3]), "r"(b0), "r"(b1));
}

// LAYER 0: gather+hadamard -> A, GEMM w1, +b1, stats -> store z1 (fp16)
// LAYER 1: load z1, BN1+ReLU -> A, GEMM w2, +b2, stats -> store z2 (fp16)
template <int LAYER>
__global__ __launch_bounds__(256, 2) void k_gemm(
    const float* __restrict__ x, const void* __restrict__ edges_raw,
    const float* __restrict__ W, const float* __restrict__ bias, int E) {
    extern __shared__ char smem_raw[];
    half* As = reinterpret_cast<half*>(smem_raw);
    half* Bs = As + MT * SROW;
    float* sSum   = reinterpret_cast<float*>(Bs + 128 * SROW);
    float* sSq    = sSum + 128;
    float* sBias  = sSq + 128;
    float* sScale = sBias + 128;
    float* sShift = sScale + 128;

    const int tid = threadIdx.x;
    const long long e0 = (long long)blockIdx.x * MT;

    // Load W transposed into Bs: Bs[n][k] = W[k][n]  (B operand, col-major KxN)
    for (int idx = tid; idx < 128 * 128; idx += 256) {
        int k = idx >> 7, n = idx & 127;
        Bs[n * SROW + k] = __float2half_rn(W[idx]);
    }
    if (tid < 128) {
        sSum[tid] = 0.f; sSq[tid] = 0.f; sBias[tid] = bias[tid];
        if (LAYER == 1) { sScale[tid] = g_scale[0][tid]; sShift[tid] = g_shift[0][tid]; }
    }

    if (LAYER == 0) {
        // gather + hadamard into As (fp16). 2 threads per row (64 ch each).
        int r = tid >> 1, t2 = tid & 1;
        long long e = e0 + r;
        half* dst = As + r * SROW + t2 * 64;
        if (e < E) {
            long long ia, ib;
            if (g_is64) {
                const long long* e64 = (const long long*)edges_raw;
                ia = e64[e];
                ib = e64[(long long)E + e];
            } else {
                const int* e32 = (const int*)edges_raw;
                ia = e32[e];
                ib = e32[(long long)E + e];
            }
            const float4* xa = reinterpret_cast<const float4*>(x + ia * 128) + t2 * 16;
            const float4* xb = reinterpret_cast<const float4*>(x + ib * 128) + t2 * 16;
#pragma unroll
            for (int i = 0; i < 16; i++) {
                float4 va = xa[i], vb = xb[i];
                half2 h0 = __floats2half2_rn(va.x * vb.x, va.y * vb.y);
                half2 h1 = __floats2half2_rn(va.z * vb.z, va.w * vb.w);
                reinterpret_cast<half2*>(dst)[2 * i]     = h0;
                reinterpret_cast<half2*>(dst)[2 * i + 1] = h1;
            }
        } else {
            half2 z = __floats2half2_rn(0.f, 0.f);
#pragma unroll
            for (int i = 0; i < 16; i++) {
                reinterpret_cast<half2*>(dst)[2 * i]     = z;
                reinterpret_cast<half2*>(dst)[2 * i + 1] = z;
            }
        }
        __syncthreads();
    } else {
        __syncthreads();  // sScale/sShift ready
        // load z1 tile, BN1+ReLU, into As (fp16)
#pragma unroll
        for (int i = 0; i < 8; i++) {
            int linear = tid + i * 256;          // 0..2047
            int r = linear >> 4, c16 = linear & 15;
            long long e = e0 + r;
            uint4 outv;
            if (e < E) {
                uint4 v = *reinterpret_cast<const uint4*>(g_z1 + e * 128 + c16 * 8);
                const half* zh = reinterpret_cast<const half*>(&v);
                half hh[8];
#pragma unroll
                for (int c = 0; c < 8; c++) {
                    int ch = c16 * 8 + c;
                    float zf = __half2float(zh[c]);
                    float h = fmaxf(fmaf(zf, sScale[ch], sShift[ch]), 0.f);
                    hh[c] = __float2half_rn(h);
                }
                outv = *reinterpret_cast<uint4*>(hh);
            } else {
                outv = make_uint4(0u, 0u, 0u, 0u);
            }
            *reinterpret_cast<uint4*>(As + r * SROW + c16 * 8) = outv;
        }
        __syncthreads();
    }

    // ---- GEMM: 128x128x128 per block, 8 warps, warp tile 32x64 ----
    const int lane = tid & 31, warp = tid >> 5;
    const int g = lane >> 2, t = lane & 3;
    const int wm = warp & 3, wn = warp >> 2;
    const int row0 = wm * 32, col0 = wn * 64;

    float acc[2][8][4];
#pragma unroll
    for (int m = 0; m < 2; m++)
#pragma unroll
        for (int j = 0; j < 8; j++)
#pragma unroll
            for (int q = 0; q < 4; q++) acc[m][j][q] = 0.f;

#pragma unroll
    for (int kk = 0; kk < 128; kk += 16) {
        uint32_t af[2][4];
#pragma unroll
        for (int m = 0; m < 2; m++) {
            const half* ap = As + (row0 + 16 * m + g) * SROW + kk + 2 * t;
            af[m][0] = *reinterpret_cast<const uint32_t*>(ap);
            af[m][1] = *reinterpret_cast<const uint32_t*>(ap + 8 * SROW);
            af[m][2] = *reinterpret_cast<const uint32_t*>(ap + 8);
            af[m][3] = *reinterpret_cast<const uint32_t*>(ap + 8 * SROW + 8);
        }
#pragma unroll
        for (int j = 0; j < 8; j++) {
            const half* bp = Bs + (col0 + 8 * j + g) * SROW + kk + 2 * t;
            uint32_t b0 = *reinterpret_cast<const uint32_t*>(bp);
            uint32_t b1 = *reinterpret_cast<const uint32_t*>(bp + 8);
            mma16816(acc[0][j], af[0], b0, b1);
            mma16816(acc[1][j], af[1], b0, b1);
        }
    }

    // ---- bias + per-channel stats (sum, sumsq) ----
#pragma unroll
    for (int j = 0; j < 8; j++) {
        int cA = col0 + 8 * j + 2 * t;
        float bA = sBias[cA], bB = sBias[cA + 1];
        float s0 = 0.f, s1 = 0.f, q0 = 0.f, q1 = 0.f;
#pragma unroll
        for (int m = 0; m < 2; m++) {
            float* c = acc[m][j];
            c[0] += bA; c[1] += bB; c[2] += bA; c[3] += bB;
            s0 += c[0] + c[2];           s1 += c[1] + c[3];
            q0 += c[0] * c[0] + c[2] * c[2];
            q1 += c[1] * c[1] + c[3] * c[3];
        }
#pragma unroll
        for (int off = 4; off < 32; off <<= 1) {
            s0 += __shfl_xor_sync(0xffffffffu, s0, off);
            s1 += __shfl_xor_sync(0xffffffffu, s1, off);
            q0 += __shfl_xor_sync(0xffffffffu, q0, off);
            q1 += __shfl_xor_sync(0xffffffffu, q1, off);
        }
        if (lane < 4) {
            atomicAdd(&sSum[cA], s0); atomicAdd(&sSum[cA + 1], s1);
            atomicAdd(&sSq[cA], q0);  atomicAdd(&sSq[cA + 1], q1);
        }
    }

    __syncthreads();  // all As reads + smem stat adds done

    // ---- stage z tile (fp16) back into As for coalesced global store ----
#pragma unroll
    for (int j = 0; j < 8; j++) {
        int cc = col0 + 8 * j + 2 * t;
#pragma unroll
        for (int m = 0; m < 2; m++) {
            int r = row0 + 16 * m + g;
            *reinterpret_cast<half2*>(As + r * SROW + cc) =
                __floats2half2_rn(acc[m][j][0], acc[m][j][1]);
            *reinterpret_cast<half2*>(As + (r + 8) * SROW + cc) =
                __floats2half2_rn(acc[m][j][2], acc[m][j][3]);
        }
    }
    __syncthreads();

    if (tid < 128) {
        atomicAdd(&g_s[LAYER][tid], sSum[tid]);
        atomicAdd(&g_q[LAYER][tid], sSq[tid]);
    }

    half* Z = (LAYER == 0) ? g_z1 : g_z2;
#pragma unroll
    for (int i = 0; i < 8; i++) {
        int linear = tid + i * 256;
        int r = linear >> 4, c16 = linear & 15;
        long long e = e0 + r;
        if (e < E) {
            *reinterpret_cast<uint4*>(Z + e * 128 + c16 * 8) =
                *reinterpret_cast<const uint4*>(As + r * SROW + c16 * 8);
        }
    }
}

// Finalize BN stats (with analytic pad-row correction: P rows of z == bias).
__global__ void k_finalize(const float* __restrict__ bias,
                           const float* __restrict__ gamma,
                           const float* __restrict__ beta,
                           int layer, int E, int P) {
    int c = threadIdx.x;
    float b = bias[c];
    float S = g_s[layer][c] - (float)P * b;
    float Q = g_q[layer][c] - (float)P * b * b;
    float invE = 1.0f / (float)E;
    float mean = S * invE;
    float var = Q * invE - mean * mean;
    float sc = gamma[c] * rsqrtf(var + 1e-5f);
    g_scale[layer][c] = sc;
    g_shift[layer][c] = fmaf(-mean, sc, beta[c]);
}

// Final: h2 = relu(BN2(z2)); out = h2@wc + bc. One warp per edge-row.
__global__ void k_out(const float* __restrict__ wc, const float* __restrict__ bc,
                      float* __restrict__ out, int E) {
    int lane = threadIdx.x & 31;
    int warpG = (blockIdx.x * blockDim.x + threadIdx.x) >> 5;
    int nW = (gridDim.x * blockDim.x) >> 5;
    int c0 = lane * 4;
    float sc[4], sh[4], w[4];
#pragma unroll
    for (int i = 0; i < 4; i++) {
        sc[i] = g_scale[1][c0 + i];
        sh[i] = g_shift[1][c0 + i];
        w[i]  = wc[c0 + i];
    }
    float b = bc[0];
    for (long long e = warpG; e < E; e += nW) {
        uint2 v = *reinterpret_cast<const uint2*>(g_z2 + e * 128 + c0);
        const half* zh = reinterpret_cast<const half*>(&v);
        float accv = 0.f;
#pragma unroll
        for (int i = 0; i < 4; i++) {
            float zf = __half2float(zh[i]);
            float h = fmaxf(fmaf(zf, sc[i], sh[i]), 0.f);
            accv = fmaf(h, w[i], accv);
        }
#pragma unroll
        for (int off = 16; off > 0; off >>= 1)
            accv += __shfl_xor_sync(0xffffffffu, accv, off);
        if (lane == 0) out[e] = accv + b;
    }
}

extern "C" void kernel_launch(void* const* d_in, const int* in_sizes, int n_in,
                              void* d_out, int out_size) {
    const float* x     = (const float*)d_in[0];
    const void*  edges = d_in[1];
    const float* w1 = (const float*)d_in[2];
    const float* b1 = (const float*)d_in[3];
    const float* g1 = (const float*)d_in[4];
    const float* be1 = (const float*)d_in[5];
    const float* w2 = (const float*)d_in[6];
    const float* b2 = (const float*)d_in[7];
    const float* g2 = (const float*)d_in[8];
    const float* be2 = (const float*)d_in[9];
    const float* wc = (const float*)d_in[10];
    const float* bc = (const float*)d_in[11];
    float* out = (float*)d_out;

    int E = in_sizes[1] / 2;
    int NB = (E + MT - 1) / MT;
    int P = NB * MT - E;

    size_t smem = (size_t)(MT * SROW + 128 * SROW) * sizeof(half) + 5 * 128 * sizeof(float);

    cudaFuncSetAttribute(k_gemm<0>, cudaFuncAttributeMaxDynamicSharedMemorySize, (int)smem);
    cudaFuncSetAttribute(k_gemm<1>, cudaFuncAttributeMaxDynamicSharedMemorySize, (int)smem);

    k_detect<<<1, 128>>>(edges);
    k_gemm<0><<<NB, 256, smem>>>(x, edges, w1, b1, E);
    k_finalize<<<1, 128>>>(b1, g1, be1, 0, E, P);
    k_gemm<1><<<NB, 256, smem>>>(x, edges, w2, b2, E);
    k_finalize<<<1, 128>>>(b2, g2, be2, 1, E, P);
    k_out<<<2048, 256>>>(wc, bc, out, E);
}

// round 4
// speedup vs baseline: 1.1914x; 1.1914x over previous
#include <cuda_runtime.h>
#include <cuda_fp16.h>
#include <cstdint>

// ---------------------------------------------------------------------------
// CELP edge-MLP, round 4: ldmatrix mainloop + conflict-free W staging.
//   x_ij = x[e0]*x[e1] ; z1 = x_ij@w1+b1 ; h1 = relu(BN1(z1))
//   z2 = h1@w2+b2 ; h2 = relu(BN2(z2)) ; out = h2@wc+bc
// ---------------------------------------------------------------------------

#define EMAX 1000000
#define MT 128          // rows (edges) per block tile
#define SROW 136        // smem row stride in halfs (272B = 17*16B, conflict-free)

static __device__ __half g_z1[(size_t)EMAX * 128];
static __device__ __half g_z2[(size_t)EMAX * 128];
static __device__ float g_s[2][128];
static __device__ float g_q[2][128];
static __device__ float g_scale[2][128];
static __device__ float g_shift[2][128];
static __device__ int g_is64;

__global__ void k_detect(const void* edges) {
    const long long* e64 = (const long long*)edges;
    int is64 = 1;
    for (int i = 0; i < 8; i++) {
        long long v = e64[i];
        if (v < 0 || v >= (1LL << 31)) is64 = 0;
    }
    g_is64 = is64;
    int t = threadIdx.x;
    if (t < 128) {
        g_s[0][t] = 0.f; g_s[1][t] = 0.f;
        g_q[0][t] = 0.f; g_q[1][t] = 0.f;
    }
}

__device__ __forceinline__ void mma16816(float* c, const uint32_t* a,
                                         uint32_t b0, uint32_t b1) {
    asm volatile(
        "mma.sync.aligned.m16n8k16.row.col.f32.f16.f16.f32 "
        "{%0,%1,%2,%3}, {%4,%5,%6,%7}, {%8,%9}, {%0,%1,%2,%3};\n"
        : "+f"(c[0]), "+f"(c[1]), "+f"(c[2]), "+f"(c[3])
        : "r"(a[0]), "r"(a[1]), "r"(a[2]), "r"(a[3]), "r"(b0), "r"(b1));
}

__device__ __forceinline__ void ldsm_x4(uint32_t addr, uint32_t* r) {
    asm volatile("ldmatrix.sync.aligned.m8n8.x4.shared.b16 {%0,%1,%2,%3}, [%4];"
                 : "=r"(r[0]), "=r"(r[1]), "=r"(r[2]), "=r"(r[3]) : "r"(addr));
}
__device__ __forceinline__ void ldsm_x4_t(uint32_t addr, uint32_t* r) {
    asm volatile("ldmatrix.sync.aligned.m8n8.x4.trans.shared.b16 {%0,%1,%2,%3}, [%4];"
                 : "=r"(r[0]), "=r"(r[1]), "=r"(r[2]), "=r"(r[3]) : "r"(addr));
}

// LAYER 0: gather+hadamard -> A, GEMM w1, +b1, stats -> store z1 (fp16)
// LAYER 1: load z1, BN1+ReLU -> A, GEMM w2, +b2, stats -> store z2 (fp16)
template <int LAYER>
__global__ __launch_bounds__(256, 2) void k_gemm(
    const float* __restrict__ x, const void* __restrict__ edges_raw,
    const float* __restrict__ W, const float* __restrict__ bias, int E) {
    extern __shared__ char smem_raw[];
    half* As = reinterpret_cast<half*>(smem_raw);
    half* Ws = As + MT * SROW;                       // W row-major [k][n]
    float* sSum   = reinterpret_cast<float*>(Ws + 128 * SROW);
    float* sSq    = sSum + 128;
    float* sBias  = sSq + 128;
    float* sScale = sBias + 128;
    float* sShift = sScale + 128;

    const int tid = threadIdx.x;
    const long long e0 = (long long)blockIdx.x * MT;

    // ---- stage W row-major (no transpose), vectorized, conflict-free ----
    {
        const float4* Wv = reinterpret_cast<const float4*>(W);
#pragma unroll
        for (int i = 0; i < 16; i++) {
            int f4 = tid + i * 256;              // 0..4095
            int k = f4 >> 5, n4 = (f4 & 31) << 2;
            float4 v = Wv[f4];
            half2* dst = reinterpret_cast<half2*>(Ws + k * SROW + n4);
            dst[0] = __floats2half2_rn(v.x, v.y);
            dst[1] = __floats2half2_rn(v.z, v.w);
        }
    }
    if (tid < 128) {
        sSum[tid] = 0.f; sSq[tid] = 0.f; sBias[tid] = bias[tid];
        if (LAYER == 1) { sScale[tid] = g_scale[0][tid]; sShift[tid] = g_shift[0][tid]; }
    }

    if (LAYER == 0) {
        // gather + hadamard into As (fp16). 2 threads per row (64 ch each).
        int r = tid >> 1, t2 = tid & 1;
        long long e = e0 + r;
        half* dst = As + r * SROW + t2 * 64;
        if (e < E) {
            long long ia, ib;
            if (g_is64) {
                const long long* e64 = (const long long*)edges_raw;
                ia = e64[e];
                ib = e64[(long long)E + e];
            } else {
                const int* e32 = (const int*)edges_raw;
                ia = e32[e];
                ib = e32[(long long)E + e];
            }
            const float4* xa = reinterpret_cast<const float4*>(x + ia * 128) + t2 * 16;
            const float4* xb = reinterpret_cast<const float4*>(x + ib * 128) + t2 * 16;
#pragma unroll
            for (int i = 0; i < 16; i++) {
                float4 va = xa[i], vb = xb[i];
                half2 h0 = __floats2half2_rn(va.x * vb.x, va.y * vb.y);
                half2 h1 = __floats2half2_rn(va.z * vb.z, va.w * vb.w);
                reinterpret_cast<half2*>(dst)[2 * i]     = h0;
                reinterpret_cast<half2*>(dst)[2 * i + 1] = h1;
            }
        } else {
            half2 z = __floats2half2_rn(0.f, 0.f);
#pragma unroll
            for (int i = 0; i < 16; i++) {
                reinterpret_cast<half2*>(dst)[2 * i]     = z;
                reinterpret_cast<half2*>(dst)[2 * i + 1] = z;
            }
        }
        __syncthreads();
    } else {
        __syncthreads();  // sScale/sShift ready
        // load z1 tile, BN1+ReLU, into As (fp16)
#pragma unroll
        for (int i = 0; i < 8; i++) {
            int linear = tid + i * 256;          // 0..2047
            int r = linear >> 4, c16 = linear & 15;
            long long e = e0 + r;
            uint4 outv;
            if (e < E) {
                uint4 v = *reinterpret_cast<const uint4*>(g_z1 + e * 128 + c16 * 8);
                const half* zh = reinterpret_cast<const half*>(&v);
                half hh[8];
#pragma unroll
                for (int c = 0; c < 8; c++) {
                    int ch = c16 * 8 + c;
                    float zf = __half2float(zh[c]);
                    float h = fmaxf(fmaf(zf, sScale[ch], sShift[ch]), 0.f);
                    hh[c] = __float2half_rn(h);
                }
                outv = *reinterpret_cast<uint4*>(hh);
            } else {
                outv = make_uint4(0u, 0u, 0u, 0u);
            }
            *reinterpret_cast<uint4*>(As + r * SROW + c16 * 8) = outv;
        }
        __syncthreads();
    }

    // ---- GEMM: 128x128x128 per block, 8 warps, warp tile 32x64, LDSM ----
    const int lane = tid & 31, warp = tid >> 5;
    const int t = lane & 3;
    const int wm = warp & 3, wn = warp >> 2;
    const int row0 = wm * 32, col0 = wn * 64;

    const int b3 = (lane >> 3) & 1, b4 = (lane >> 4) & 1, r8 = lane & 7;
    uint32_t As_b = (uint32_t)__cvta_generic_to_shared(As);
    uint32_t Ws_b = (uint32_t)__cvta_generic_to_shared(Ws);
    // A frag addr: row = row0 + 16m + 8*b3 + r8 ; col = kk + 8*b4
    uint32_t a_off = As_b + (uint32_t)(((row0 + 8 * b3 + r8) * SROW + 8 * b4) * 2);
    // B frag addr: k = kk + 8*b3 + r8 ; n = col0 + 16p + 8*b4
    uint32_t b_off = Ws_b + (uint32_t)(((8 * b3 + r8) * SROW + col0 + 8 * b4) * 2);

    float acc[2][8][4];
#pragma unroll
    for (int m = 0; m < 2; m++)
#pragma unroll
        for (int j = 0; j < 8; j++)
#pragma unroll
            for (int q = 0; q < 4; q++) acc[m][j][q] = 0.f;

#pragma unroll
    for (int kk = 0; kk < 128; kk += 16) {
        uint32_t a0[4], a1[4];
        ldsm_x4(a_off + kk * 2, a0);
        ldsm_x4(a_off + (16 * SROW + kk) * 2, a1);
        uint32_t bf[4][4];
#pragma unroll
        for (int p = 0; p < 4; p++)
            ldsm_x4_t(b_off + (kk * SROW + 16 * p) * 2, bf[p]);
#pragma unroll
        for (int j = 0; j < 8; j++) {
            uint32_t bb0 = bf[j >> 1][(j & 1) * 2];
            uint32_t bb1 = bf[j >> 1][(j & 1) * 2 + 1];
            mma16816(acc[0][j], a0, bb0, bb1);
            mma16816(acc[1][j], a1, bb0, bb1);
        }
    }

    // ---- bias + per-channel stats (sum, sumsq) ----
#pragma unroll
    for (int j = 0; j < 8; j++) {
        int cA = col0 + 8 * j + 2 * t;
        float bA = sBias[cA], bB = sBias[cA + 1];
        float s0 = 0.f, s1 = 0.f, q0 = 0.f, q1 = 0.f;
#pragma unroll
        for (int m = 0; m < 2; m++) {
            float* c = acc[m][j];
            c[0] += bA; c[1] += bB; c[2] += bA; c[3] += bB;
            s0 += c[0] + c[2];           s1 += c[1] + c[3];
            q0 += c[0] * c[0] + c[2] * c[2];
            q1 += c[1] * c[1] + c[3] * c[3];
        }
#pragma unroll
        for (int off = 4; off < 32; off <<= 1) {
            s0 += __shfl_xor_sync(0xffffffffu, s0, off);
            s1 += __shfl_xor_sync(0xffffffffu, s1, off);
            q0 += __shfl_xor_sync(0xffffffffu, q0, off);
            q1 += __shfl_xor_sync(0xffffffffu, q1, off);
        }
        if (lane < 4) {
            atomicAdd(&sSum[cA], s0); atomicAdd(&sSum[cA + 1], s1);
            atomicAdd(&sSq[cA], q0);  atomicAdd(&sSq[cA + 1], q1);
        }
    }

    __syncthreads();  // all As reads + smem stat adds done

    // ---- stage z tile (fp16) back into As for coalesced global store ----
    {
        const int g = lane >> 2;
#pragma unroll
        for (int j = 0; j < 8; j++) {
            int cc = col0 + 8 * j + 2 * t;
#pragma unroll
            for (int m = 0; m < 2; m++) {
                int r = row0 + 16 * m + g;
                *reinterpret_cast<half2*>(As + r * SROW + cc) =
                    __floats2half2_rn(acc[m][j][0], acc[m][j][1]);
                *reinterpret_cast<half2*>(As + (r + 8) * SROW + cc) =
                    __floats2half2_rn(acc[m][j][2], acc[m][j][3]);
            }
        }
    }
    __syncthreads();

    if (tid < 128) {
        atomicAdd(&g_s[LAYER][tid], sSum[tid]);
        atomicAdd(&g_q[LAYER][tid], sSq[tid]);
    }

    half* Z = (LAYER == 0) ? g_z1 : g_z2;
#pragma unroll
    for (int i = 0; i < 8; i++) {
        int linear = tid + i * 256;
        int r = linear >> 4, c16 = linear & 15;
        long long e = e0 + r;
        if (e < E) {
            *reinterpret_cast<uint4*>(Z + e * 128 + c16 * 8) =
                *reinterpret_cast<const uint4*>(As + r * SROW + c16 * 8);
        }
    }
}

// Finalize BN stats (analytic pad-row correction: P rows of z == bias).
__global__ void k_finalize(const float* __restrict__ bias,
                           const float* __restrict__ gamma,
                           const float* __restrict__ beta,
                           int layer, int E, int P) {
    int c = threadIdx.x;
    float b = bias[c];
    float S = g_s[layer][c] - (float)P * b;
    float Q = g_q[layer][c] - (float)P * b * b;
    float invE = 1.0f / (float)E;
    float mean = S * invE;
    float var = Q * invE - mean * mean;
    float sc = gamma[c] * rsqrtf(var + 1e-5f);
    g_scale[layer][c] = sc;
    g_shift[layer][c] = fmaf(-mean, sc, beta[c]);
}

// Final: h2 = relu(BN2(z2)); out = h2@wc + bc. One warp per edge-row.
__global__ void k_out(const float* __restrict__ wc, const float* __restrict__ bc,
                      float* __restrict__ out, int E) {
    int lane = threadIdx.x & 31;
    int warpG = (blockIdx.x * blockDim.x + threadIdx.x) >> 5;
    int nW = (gridDim.x * blockDim.x) >> 5;
    int c0 = lane * 4;
    float sc[4], sh[4], w[4];
#pragma unroll
    for (int i = 0; i < 4; i++) {
        sc[i] = g_scale[1][c0 + i];
        sh[i] = g_shift[1][c0 + i];
        w[i]  = wc[c0 + i];
    }
    float b = bc[0];
    for (long long e = warpG; e < E; e += nW) {
        uint2 v = *reinterpret_cast<const uint2*>(g_z2 + e * 128 + c0);
        const half* zh = reinterpret_cast<const half*>(&v);
        float accv = 0.f;
#pragma unroll
        for (int i = 0; i < 4; i++) {
            float zf = __half2float(zh[i]);
            float h = fmaxf(fmaf(zf, sc[i], sh[i]), 0.f);
            accv = fmaf(h, w[i], accv);
        }
#pragma unroll
        for (int off = 16; off > 0; off >>= 1)
            accv += __shfl_xor_sync(0xffffffffu, accv, off);
        if (lane == 0) out[e] = accv + b;
    }
}

extern "C" void kernel_launch(void* const* d_in, const int* in_sizes, int n_in,
                              void* d_out, int out_size) {
    const float* x     = (const float*)d_in[0];
    const void*  edges = d_in[1];
    const float* w1 = (const float*)d_in[2];
    const float* b1 = (const float*)d_in[3];
    const float* g1 = (const float*)d_in[4];
    const float* be1 = (const float*)d_in[5];
    const float* w2 = (const float*)d_in[6];
    const float* b2 = (const float*)d_in[7];
    const float* g2 = (const float*)d_in[8];
    const float* be2 = (const float*)d_in[9];
    const float* wc = (const float*)d_in[10];
    const float* bc = (const float*)d_in[11];
    float* out = (float*)d_out;

    int E = in_sizes[1] / 2;
    int NB = (E + MT - 1) / MT;
    int P = NB * MT - E;

    size_t smem = (size_t)(MT * SROW + 128 * SROW) * sizeof(half) + 5 * 128 * sizeof(float);

    cudaFuncSetAttribute(k_gemm<0>, cudaFuncAttributeMaxDynamicSharedMemorySize, (int)smem);
    cudaFuncSetAttribute(k_gemm<1>, cudaFuncAttributeMaxDynamicSharedMemorySize, (int)smem);

    k_detect<<<1, 128>>>(edges);
    k_gemm<0><<<NB, 256, smem>>>(x, edges, w1, b1, E);
    k_finalize<<<1, 128>>>(b1, g1, be1, 0, E, P);
    k_gemm<1><<<NB, 256, smem>>>(x, edges, w2, b2, E);
    k_finalize<<<1, 128>>>(b2, g2, be2, 1, E, P);
    k_out<<<2048, 256>>>(wc, bc, out, E);
}

// round 6
// speedup vs baseline: 1.2086x; 1.0144x over previous
#include <cuda_runtime.h>
#include <cuda_fp16.h>
#include <cstdint>

// ---------------------------------------------------------------------------
// CELP edge-MLP, round 6: legacy-MMA path (target is sm_100 baseline, no
// tcgen05). LDSM mainloop + STSM epilogue + cp.async fp16 W staging.
//   x_ij = x[e0]*x[e1] ; z1 = x_ij@w1+b1 ; h1 = relu(BN1(z1))
//   z2 = h1@w2+b2 ; h2 = relu(BN2(z2)) ; out = h2@wc+bc
// ---------------------------------------------------------------------------

#define EMAX 1000000
#define MT 128          // rows (edges) per block tile
#define SROW 136        // smem row stride in halfs (272B, conflict-free)

static __device__ __half g_z1[(size_t)EMAX * 128];
static __device__ __half g_z2[(size_t)EMAX * 128];
static __device__ __half g_wt[2][128 * 128];   // fp16 copy of W: [layer][k][n]
static __device__ float g_s[2][128];
static __device__ float g_q[2][128];
static __device__ float g_scale[2][128];
static __device__ float g_shift[2][128];
static __device__ int g_is64;

// prep: fp16 W, zero stats, edge dtype detect
__global__ void k_prep(const void* edges, const float* __restrict__ w1,
                       const float* __restrict__ w2) {
    int idx = blockIdx.x * 256 + threadIdx.x;   // 0..32767
    int layer = idx >> 14, rem = idx & 16383;
    const float* W = layer ? w2 : w1;
    g_wt[layer][rem] = __float2half_rn(W[rem]);
    if (blockIdx.x == 0) {
        int t = threadIdx.x;
        if (t < 128) {
            g_s[0][t] = 0.f; g_s[1][t] = 0.f;
            g_q[0][t] = 0.f; g_q[1][t] = 0.f;
        }
        if (t == 0) {
            const long long* e64 = (const long long*)edges;
            int is64 = 1;
            for (int i = 0; i < 8; i++) {
                long long v = e64[i];
                if (v < 0 || v >= (1LL << 31)) is64 = 0;
            }
            g_is64 = is64;
        }
    }
}

__device__ __forceinline__ void mma16816(float* c, const uint32_t* a,
                                         uint32_t b0, uint32_t b1) {
    asm volatile(
        "mma.sync.aligned.m16n8k16.row.col.f32.f16.f16.f32 "
        "{%0,%1,%2,%3}, {%4,%5,%6,%7}, {%8,%9}, {%0,%1,%2,%3};\n"
        : "+f"(c[0]), "+f"(c[1]), "+f"(c[2]), "+f"(c[3])
        : "r"(a[0]), "r"(a[1]), "r"(a[2]), "r"(a[3]), "r"(b0), "r"(b1));
}
__device__ __forceinline__ void ldsm_x4(uint32_t addr, uint32_t* r) {
    asm volatile("ldmatrix.sync.aligned.m8n8.x4.shared.b16 {%0,%1,%2,%3}, [%4];"
                 : "=r"(r[0]), "=r"(r[1]), "=r"(r[2]), "=r"(r[3]) : "r"(addr));
}
__device__ __forceinline__ void ldsm_x4_t(uint32_t addr, uint32_t* r) {
    asm volatile("ldmatrix.sync.aligned.m8n8.x4.trans.shared.b16 {%0,%1,%2,%3}, [%4];"
                 : "=r"(r[0]), "=r"(r[1]), "=r"(r[2]), "=r"(r[3]) : "r"(addr));
}
__device__ __forceinline__ void stsm_x4(uint32_t addr, uint32_t r0, uint32_t r1,
                                        uint32_t r2, uint32_t r3) {
    asm volatile("stmatrix.sync.aligned.m8n8.x4.shared.b16 [%0], {%1,%2,%3,%4};"
                 :: "r"(addr), "r"(r0), "r"(r1), "r"(r2), "r"(r3) : "memory");
}
#define CP_ASYNC16(dst, src) \
    asm volatile("cp.async.cg.shared.global [%0], [%1], 16;" :: "r"(dst), "l"(src))
#define CP_COMMIT() asm volatile("cp.async.commit_group;" ::: "memory")
#define CP_WAIT0()  asm volatile("cp.async.wait_group 0;" ::: "memory")

// LAYER 0: gather+hadamard -> A, GEMM w1, +b1, stats -> store z1 (fp16)
// LAYER 1: load z1, BN1+ReLU -> A, GEMM w2, +b2, stats -> store z2 (fp16)
template <int LAYER>
__global__ __launch_bounds__(256, 2) void k_gemm(
    const float* __restrict__ x, const void* __restrict__ edges_raw,
    const float* __restrict__ bias, int E) {
    extern __shared__ char smem_raw[];
    half* As = reinterpret_cast<half*>(smem_raw);
    half* Ws = As + MT * SROW;                       // W row-major [k][n], fp16
    float* sSum   = reinterpret_cast<float*>(Ws + 128 * SROW);
    float* sSq    = sSum + 128;
    float* sBias  = sSq + 128;
    float* sScale = sBias + 128;
    float* sShift = sScale + 128;

    const int tid = threadIdx.x;
    const long long e0 = (long long)blockIdx.x * MT;
    const uint32_t As_b = (uint32_t)__cvta_generic_to_shared(As);
    const uint32_t Ws_b = (uint32_t)__cvta_generic_to_shared(Ws);

    // ---- stage fp16 W via cp.async (8 x 16B per thread, conflict-free) ----
    {
        const half* WT = g_wt[LAYER];
#pragma unroll
        for (int it = 0; it < 8; it++) {
            int idx = tid + it * 256;            // 0..2047
            int k = idx >> 4, n16 = idx & 15;
            uint32_t dst = Ws_b + (uint32_t)((k * SROW + n16 * 8) * 2);
            CP_ASYNC16(dst, WT + k * 128 + n16 * 8);
        }
        CP_COMMIT();
    }
    if (tid < 128) {
        sSum[tid] = 0.f; sSq[tid] = 0.f; sBias[tid] = bias[tid];
        if (LAYER == 1) { sScale[tid] = g_scale[0][tid]; sShift[tid] = g_shift[0][tid]; }
    }

    if (LAYER == 0) {
        // gather + hadamard into As (fp16). 2 threads per row (64 ch each).
        int r = tid >> 1, t2 = tid & 1;
        long long e = e0 + r;
        half* dst = As + r * SROW + t2 * 64;
        if (e < E) {
            long long ia, ib;
            if (g_is64) {
                const long long* e64 = (const long long*)edges_raw;
                ia = e64[e]; ib = e64[(long long)E + e];
            } else {
                const int* e32 = (const int*)edges_raw;
                ia = e32[e]; ib = e32[(long long)E + e];
            }
            const float4* xa = reinterpret_cast<const float4*>(x + ia * 128) + t2 * 16;
            const float4* xb = reinterpret_cast<const float4*>(x + ib * 128) + t2 * 16;
#pragma unroll
            for (int i = 0; i < 16; i++) {
                float4 va = xa[i], vb = xb[i];
                half2 h0 = __floats2half2_rn(va.x * vb.x, va.y * vb.y);
                half2 h1 = __floats2half2_rn(va.z * vb.z, va.w * vb.w);
                reinterpret_cast<half2*>(dst)[2 * i]     = h0;
                reinterpret_cast<half2*>(dst)[2 * i + 1] = h1;
            }
        } else {
            half2 z = __floats2half2_rn(0.f, 0.f);
#pragma unroll
            for (int i = 0; i < 16; i++) {
                reinterpret_cast<half2*>(dst)[2 * i]     = z;
                reinterpret_cast<half2*>(dst)[2 * i + 1] = z;
            }
        }
        CP_WAIT0();
        __syncthreads();
    } else {
        __syncthreads();  // sScale/sShift ready
        // load z1 tile, BN1+ReLU, into As (fp16)
#pragma unroll
        for (int i = 0; i < 8; i++) {
            int linear = tid + i * 256;          // 0..2047
            int r = linear >> 4, c16 = linear & 15;
            long long e = e0 + r;
            uint4 outv;
            if (e < E) {
                uint4 v = *reinterpret_cast<const uint4*>(g_z1 + e * 128 + c16 * 8);
                const half* zh = reinterpret_cast<const half*>(&v);
                half hh[8];
#pragma unroll
                for (int c = 0; c < 8; c++) {
                    int ch = c16 * 8 + c;
                    float zf = __half2float(zh[c]);
                    float h = fmaxf(fmaf(zf, sScale[ch], sShift[ch]), 0.f);
                    hh[c] = __float2half_rn(h);
                }
                outv = *reinterpret_cast<uint4*>(hh);
            } else {
                outv = make_uint4(0u, 0u, 0u, 0u);
            }
            *reinterpret_cast<uint4*>(As + r * SROW + c16 * 8) = outv;
        }
        CP_WAIT0();
        __syncthreads();
    }

    // ---- GEMM: 128x128x128 per block, 8 warps, warp tile 32x64, LDSM ----
    const int lane = tid & 31, warp = tid >> 5;
    const int t = lane & 3;
    const int wm = warp & 3, wn = warp >> 2;
    const int row0 = wm * 32, col0 = wn * 64;

    const int b3 = (lane >> 3) & 1, b4 = (lane >> 4) & 1, r8 = lane & 7;
    // A frag addr: row = row0 + 16m + 8*b3 + r8 ; col = kk + 8*b4
    uint32_t a_off = As_b + (uint32_t)(((row0 + 8 * b3 + r8) * SROW + 8 * b4) * 2);
    // B frag addr: k = kk + 8*b3 + r8 ; n = col0 + 16p + 8*b4
    uint32_t b_off = Ws_b + (uint32_t)(((8 * b3 + r8) * SROW + col0 + 8 * b4) * 2);

    float acc[2][8][4];
#pragma unroll
    for (int m = 0; m < 2; m++)
#pragma unroll
        for (int j = 0; j < 8; j++)
#pragma unroll
            for (int q = 0; q < 4; q++) acc[m][j][q] = 0.f;

#pragma unroll
    for (int kk = 0; kk < 128; kk += 16) {
        uint32_t a0[4], a1[4];
        ldsm_x4(a_off + kk * 2, a0);
        ldsm_x4(a_off + (16 * SROW + kk) * 2, a1);
        uint32_t bf[4][4];
#pragma unroll
        for (int p = 0; p < 4; p++)
            ldsm_x4_t(b_off + (kk * SROW + 16 * p) * 2, bf[p]);
#pragma unroll
        for (int j = 0; j < 8; j++) {
            uint32_t bb0 = bf[j >> 1][(j & 1) * 2];
            uint32_t bb1 = bf[j >> 1][(j & 1) * 2 + 1];
            mma16816(acc[0][j], a0, bb0, bb1);
            mma16816(acc[1][j], a1, bb0, bb1);
        }
    }

    // ---- bias + per-channel stats + fp16 pack (fragment domain) ----
    uint32_t h2[2][2][8];   // [m][lo/hi][j]
#pragma unroll
    for (int j = 0; j < 8; j++) {
        int cA = col0 + 8 * j + 2 * t;
        float bA = sBias[cA], bB = sBias[cA + 1];
        float s0 = 0.f, s1 = 0.f, q0 = 0.f, q1 = 0.f;
#pragma unroll
        for (int m = 0; m < 2; m++) {
            float* c = acc[m][j];
            c[0] += bA; c[1] += bB; c[2] += bA; c[3] += bB;
            s0 += c[0] + c[2];           s1 += c[1] + c[3];
            q0 += c[0] * c[0] + c[2] * c[2];
            q1 += c[1] * c[1] + c[3] * c[3];
            half2 lo = __floats2half2_rn(c[0], c[1]);
            half2 hi = __floats2half2_rn(c[2], c[3]);
            h2[m][0][j] = *reinterpret_cast<uint32_t*>(&lo);
            h2[m][1][j] = *reinterpret_cast<uint32_t*>(&hi);
        }
#pragma unroll
        for (int off = 4; off < 32; off <<= 1) {
            s0 += __shfl_xor_sync(0xffffffffu, s0, off);
            s1 += __shfl_xor_sync(0xffffffffu, s1, off);
            q0 += __shfl_xor_sync(0xffffffffu, q0, off);
            q1 += __shfl_xor_sync(0xffffffffu, q1, off);
        }
        if (lane < 4) {
            atomicAdd(&sSum[cA], s0); atomicAdd(&sSum[cA + 1], s1);
            atomicAdd(&sSq[cA], q0);  atomicAdd(&sSq[cA + 1], q1);
        }
    }

    __syncthreads();  // all As reads + smem stat adds done

    // ---- stage z tile into As via stmatrix (8 STSM per warp) ----
    {
        int jj = lane >> 3;   // matrix select within x4
#pragma unroll
        for (int m = 0; m < 2; m++)
#pragma unroll
            for (int hh = 0; hh < 2; hh++) {
                int row_base = row0 + 16 * m + 8 * hh;
                uint32_t addr = As_b +
                    (uint32_t)(((row_base + r8) * SROW + col0 + jj * 8) * 2);
                stsm_x4(addr, h2[m][hh][0], h2[m][hh][1], h2[m][hh][2], h2[m][hh][3]);
                stsm_x4(addr + 64, h2[m][hh][4], h2[m][hh][5], h2[m][hh][6], h2[m][hh][7]);
            }
    }
    __syncthreads();

    if (tid < 128) {
        atomicAdd(&g_s[LAYER][tid], sSum[tid]);
        atomicAdd(&g_q[LAYER][tid], sSq[tid]);
    }

    half* Z = (LAYER == 0) ? g_z1 : g_z2;
#pragma unroll
    for (int i = 0; i < 8; i++) {
        int linear = tid + i * 256;
        int r = linear >> 4, c16 = linear & 15;
        long long e = e0 + r;
        if (e < E) {
            *reinterpret_cast<uint4*>(Z + e * 128 + c16 * 8) =
                *reinterpret_cast<const uint4*>(As + r * SROW + c16 * 8);
        }
    }
}

// Finalize BN stats (analytic pad-row correction: P rows of z == bias).
__global__ void k_finalize(const float* __restrict__ bias,
                           const float* __restrict__ gamma,
                           const float* __restrict__ beta,
                           int layer, int E, int P) {
    int c = threadIdx.x;
    float b = bias[c];
    float S = g_s[layer][c] - (float)P * b;
    float Q = g_q[layer][c] - (float)P * b * b;
    float invE = 1.0f / (float)E;
    float mean = S * invE;
    float var = Q * invE - mean * mean;
    float sc = gamma[c] * rsqrtf(var + 1e-5f);
    g_scale[layer][c] = sc;
    g_shift[layer][c] = fmaf(-mean, sc, beta[c]);
}

// Final: h2 = relu(BN2(z2)); out = h2@wc + bc. One warp per edge-row.
__global__ void k_out(const float* __restrict__ wc, const float* __restrict__ bc,
                      float* __restrict__ out, int E) {
    int lane = threadIdx.x & 31;
    int warpG = (blockIdx.x * blockDim.x + threadIdx.x) >> 5;
    int nW = (gridDim.x * blockDim.x) >> 5;
    int c0 = lane * 4;
    float sc[4], sh[4], w[4];
#pragma unroll
    for (int i = 0; i < 4; i++) {
        sc[i] = g_scale[1][c0 + i];
        sh[i] = g_shift[1][c0 + i];
        w[i]  = wc[c0 + i];
    }
    float b = bc[0];
    for (long long e = warpG; e < E; e += nW) {
        uint2 v = *reinterpret_cast<const uint2*>(g_z2 + e * 128 + c0);
        const half* zh = reinterpret_cast<const half*>(&v);
        float accv = 0.f;
#pragma unroll
        for (int i = 0; i < 4; i++) {
            float zf = __half2float(zh[i]);
            float h = fmaxf(fmaf(zf, sc[i], sh[i]), 0.f);
            accv = fmaf(h, w[i], accv);
        }
#pragma unroll
        for (int off = 16; off > 0; off >>= 1)
            accv += __shfl_xor_sync(0xffffffffu, accv, off);
        if (lane == 0) out[e] = accv + b;
    }
}

extern "C" void kernel_launch(void* const* d_in, const int* in_sizes, int n_in,
                              void* d_out, int out_size) {
    const float* x     = (const float*)d_in[0];
    const void*  edges = d_in[1];
    const float* w1 = (const float*)d_in[2];
    const float* b1 = (const float*)d_in[3];
    const float* g1 = (const float*)d_in[4];
    const float* be1 = (const float*)d_in[5];
    const float* w2 = (const float*)d_in[6];
    const float* b2 = (const float*)d_in[7];
    const float* g2 = (const float*)d_in[8];
    const float* be2 = (const float*)d_in[9];
    const float* wc = (const float*)d_in[10];
    const float* bc = (const float*)d_in[11];
    float* out = (float*)d_out;

    int E = in_sizes[1] / 2;
    int NB = (E + MT - 1) / MT;
    int P = NB * MT - E;

    size_t smem = (size_t)(MT * SROW + 128 * SROW) * sizeof(half) + 5 * 128 * sizeof(float);
    cudaFuncSetAttribute(k_gemm<0>, cudaFuncAttributeMaxDynamicSharedMemorySize, (int)smem);
    cudaFuncSetAttribute(k_gemm<1>, cudaFuncAttributeMaxDynamicSharedMemorySize, (int)smem);

    k_prep<<<128, 256>>>(edges, w1, w2);
    k_gemm<0><<<NB, 256, smem>>>(x, edges, b1, E);
    k_finalize<<<1, 128>>>(b1, g1, be1, 0, E, P);
    k_gemm<1><<<NB, 256, smem>>>(x, edges, b2, E);
    k_finalize<<<1, 128>>>(b2, g2, be2, 1, E, P);
    k_out<<<2048, 256>>>(wc, bc, out, E);
}

// round 7
// speedup vs baseline: 1.3773x; 1.1396x over previous
#include <cuda_runtime.h>
#include <cuda_fp16.h>
#include <cstdint>

// ---------------------------------------------------------------------------
// CELP edge-MLP, round 7: scalar-instruction diet.
//  - BN1 scale folded into w2 (w2' = diag(sc1) @ w2), shift folded pre-relu:
//      h1 = sc*relu(z1_full + shp),  shp = beta/sc - mean   (sc>0)
//    -> layer-1 A-staging is pure HADD2/HMAX2 in fp16.
//  - Stats accumulated on raw z' (pre-bias); finalize adds bias analytically
//    (var is bias-invariant; pad rows contribute exactly zero).
// ---------------------------------------------------------------------------

#define EMAX 1000000
#define MT 128          // rows (edges) per block tile
#define SROW 136        // smem row stride in halfs (272B, conflict-free)

static __device__ __align__(16) __half g_z1[(size_t)EMAX * 128];
static __device__ __align__(16) __half g_z2[(size_t)EMAX * 128];
static __device__ __align__(16) __half g_w1h[128 * 128];   // fp16 w1 [k][n]
static __device__ __align__(16) __half g_w2s[128 * 128];   // fp16 sc1⊙w2 [k][n]
static __device__ __align__(16) __half g_shp_h[128];       // fp16 shp for layer-1 stage
static __device__ float g_s[2][128];
static __device__ float g_q[2][128];
static __device__ float g_scale[2][128];
static __device__ float g_shift[2][128];
static __device__ int g_is64;

// prep: fp16 w1, zero stats, edge dtype detect
__global__ void k_prep(const void* edges, const float* __restrict__ w1) {
    int idx = blockIdx.x * 256 + threadIdx.x;   // 0..16383
    g_w1h[idx] = __float2half_rn(w1[idx]);
    if (blockIdx.x == 0) {
        int t = threadIdx.x;
        if (t < 128) {
            g_s[0][t] = 0.f; g_s[1][t] = 0.f;
            g_q[0][t] = 0.f; g_q[1][t] = 0.f;
        }
        if (t == 0) {
            const long long* e64 = (const long long*)edges;
            int is64 = 1;
            for (int i = 0; i < 8; i++) {
                long long v = e64[i];
                if (v < 0 || v >= (1LL << 31)) is64 = 0;
            }
            g_is64 = is64;
        }
    }
}

// w2' = diag(sc1) @ w2 in fp16 (runs after k_finalize layer 0)
__global__ void k_scalew(const float* __restrict__ w2) {
    int idx = blockIdx.x * 256 + threadIdx.x;   // 0..16383
    int k = idx >> 7;
    g_w2s[idx] = __float2half_rn(g_scale[0][k] * w2[idx]);
}

__device__ __forceinline__ void mma16816(float* c, const uint32_t* a,
                                         uint32_t b0, uint32_t b1) {
    asm volatile(
        "mma.sync.aligned.m16n8k16.row.col.f32.f16.f16.f32 "
        "{%0,%1,%2,%3}, {%4,%5,%6,%7}, {%8,%9}, {%0,%1,%2,%3};\n"
        : "+f"(c[0]), "+f"(c[1]), "+f"(c[2]), "+f"(c[3])
        : "r"(a[0]), "r"(a[1]), "r"(a[2]), "r"(a[3]), "r"(b0), "r"(b1));
}
__device__ __forceinline__ void ldsm_x4(uint32_t addr, uint32_t* r) {
    asm volatile("ldmatrix.sync.aligned.m8n8.x4.shared.b16 {%0,%1,%2,%3}, [%4];"
                 : "=r"(r[0]), "=r"(r[1]), "=r"(r[2]), "=r"(r[3]) : "r"(addr));
}
__device__ __forceinline__ void ldsm_x4_t(uint32_t addr, uint32_t* r) {
    asm volatile("ldmatrix.sync.aligned.m8n8.x4.trans.shared.b16 {%0,%1,%2,%3}, [%4];"
                 : "=r"(r[0]), "=r"(r[1]), "=r"(r[2]), "=r"(r[3]) : "r"(addr));
}
__device__ __forceinline__ void stsm_x4(uint32_t addr, uint32_t r0, uint32_t r1,
                                        uint32_t r2, uint32_t r3) {
    asm volatile("stmatrix.sync.aligned.m8n8.x4.shared.b16 [%0], {%1,%2,%3,%4};"
                 :: "r"(addr), "r"(r0), "r"(r1), "r"(r2), "r"(r3) : "memory");
}
#define CP_ASYNC16(dst, src) \
    asm volatile("cp.async.cg.shared.global [%0], [%1], 16;" :: "r"(dst), "l"(src))
#define CP_COMMIT() asm volatile("cp.async.commit_group;" ::: "memory")
#define CP_WAIT0()  asm volatile("cp.async.wait_group 0;" ::: "memory")

// LAYER 0: gather+hadamard -> A, GEMM w1 -> raw stats, store z1=z'+b1 (fp16)
// LAYER 1: load z1, +shp, relu -> A, GEMM w2' -> raw stats, store z2=z'+b2
template <int LAYER>
__global__ __launch_bounds__(256, 2) void k_gemm(
    const float* __restrict__ x, const void* __restrict__ edges_raw,
    const float* __restrict__ bias, int E) {
    extern __shared__ char smem_raw[];
    half* As = reinterpret_cast<half*>(smem_raw);
    half* Ws = As + MT * SROW;                       // W row-major [k][n], fp16
    float* sSum   = reinterpret_cast<float*>(Ws + 128 * SROW);
    float* sSq    = sSum + 128;
    float* sBias  = sSq + 128;

    const int tid = threadIdx.x;
    const long long e0 = (long long)blockIdx.x * MT;
    const uint32_t As_b = (uint32_t)__cvta_generic_to_shared(As);
    const uint32_t Ws_b = (uint32_t)__cvta_generic_to_shared(Ws);

    // ---- stage fp16 W via cp.async (8 x 16B per thread, conflict-free) ----
    {
        const half* WT = (LAYER == 0) ? g_w1h : g_w2s;
#pragma unroll
        for (int it = 0; it < 8; it++) {
            int idx = tid + it * 256;            // 0..2047
            int k = idx >> 4, n16 = idx & 15;
            uint32_t dst = Ws_b + (uint32_t)((k * SROW + n16 * 8) * 2);
            CP_ASYNC16(dst, WT + k * 128 + n16 * 8);
        }
        CP_COMMIT();
    }
    if (tid < 128) { sSum[tid] = 0.f; sSq[tid] = 0.f; sBias[tid] = bias[tid]; }

    if (LAYER == 0) {
        // gather + hadamard into As (fp16). 2 threads per row (64 ch each).
        int r = tid >> 1, t2 = tid & 1;
        long long e = e0 + r;
        half* dst = As + r * SROW + t2 * 64;
        if (e < E) {
            long long ia, ib;
            if (g_is64) {
                const long long* e64 = (const long long*)edges_raw;
                ia = e64[e]; ib = e64[(long long)E + e];
            } else {
                const int* e32 = (const int*)edges_raw;
                ia = e32[e]; ib = e32[(long long)E + e];
            }
            const float4* xa = reinterpret_cast<const float4*>(x + ia * 128) + t2 * 16;
            const float4* xb = reinterpret_cast<const float4*>(x + ib * 128) + t2 * 16;
#pragma unroll
            for (int i = 0; i < 8; i++) {
                float4 a0 = xa[2 * i], a1 = xa[2 * i + 1];
                float4 b0 = xb[2 * i], b1 = xb[2 * i + 1];
                half2 h[4];
                h[0] = __floats2half2_rn(a0.x * b0.x, a0.y * b0.y);
                h[1] = __floats2half2_rn(a0.z * b0.z, a0.w * b0.w);
                h[2] = __floats2half2_rn(a1.x * b1.x, a1.y * b1.y);
                h[3] = __floats2half2_rn(a1.z * b1.z, a1.w * b1.w);
                *reinterpret_cast<uint4*>(dst + i * 8) = *reinterpret_cast<uint4*>(h);
            }
        } else {
            uint4 z = make_uint4(0u, 0u, 0u, 0u);
#pragma unroll
            for (int i = 0; i < 8; i++)
                *reinterpret_cast<uint4*>(dst + i * 8) = z;
        }
        CP_WAIT0();
        __syncthreads();
    } else {
        // preload this thread's 4 shift half2 (channels fixed: c16 = tid&15)
        const __half2* shp2 = reinterpret_cast<const __half2*>(g_shp_h) + (tid & 15) * 4;
        half2 sh0 = shp2[0], sh1 = shp2[1], sh2 = shp2[2], sh3 = shp2[3];
        half2 zz = __floats2half2_rn(0.f, 0.f);
#pragma unroll
        for (int i = 0; i < 8; i++) {
            int linear = tid + i * 256;          // 0..2047
            int r = linear >> 4, c16 = linear & 15;
            long long e = e0 + r;
            uint4 outv = make_uint4(0u, 0u, 0u, 0u);
            if (e < E) {
                uint4 v = *reinterpret_cast<const uint4*>(g_z1 + e * 128 + c16 * 8);
                half2* p = reinterpret_cast<half2*>(&v);
                p[0] = __hmax2(__hadd2(p[0], sh0), zz);
                p[1] = __hmax2(__hadd2(p[1], sh1), zz);
                p[2] = __hmax2(__hadd2(p[2], sh2), zz);
                p[3] = __hmax2(__hadd2(p[3], sh3), zz);
                outv = v;
            }
            *reinterpret_cast<uint4*>(As + r * SROW + c16 * 8) = outv;
        }
        CP_WAIT0();
        __syncthreads();
    }

    // ---- GEMM: 128x128x128 per block, 8 warps, warp tile 32x64, LDSM ----
    const int lane = tid & 31, warp = tid >> 5;
    const int t = lane & 3;
    const int wm = warp & 3, wn = warp >> 2;
    const int row0 = wm * 32, col0 = wn * 64;

    const int b3 = (lane >> 3) & 1, b4 = (lane >> 4) & 1, r8 = lane & 7;
    uint32_t a_off = As_b + (uint32_t)(((row0 + 8 * b3 + r8) * SROW + 8 * b4) * 2);
    uint32_t b_off = Ws_b + (uint32_t)(((8 * b3 + r8) * SROW + col0 + 8 * b4) * 2);

    float acc[2][8][4];
#pragma unroll
    for (int m = 0; m < 2; m++)
#pragma unroll
        for (int j = 0; j < 8; j++)
#pragma unroll
            for (int q = 0; q < 4; q++) acc[m][j][q] = 0.f;

#pragma unroll
    for (int kk = 0; kk < 128; kk += 16) {
        uint32_t a0[4], a1[4];
        ldsm_x4(a_off + kk * 2, a0);
        ldsm_x4(a_off + (16 * SROW + kk) * 2, a1);
        uint32_t bf[4][4];
#pragma unroll
        for (int p = 0; p < 4; p++)
            ldsm_x4_t(b_off + (kk * SROW + 16 * p) * 2, bf[p]);
#pragma unroll
        for (int j = 0; j < 8; j++) {
            uint32_t bb0 = bf[j >> 1][(j & 1) * 2];
            uint32_t bb1 = bf[j >> 1][(j & 1) * 2 + 1];
            mma16816(acc[0][j], a0, bb0, bb1);
            mma16816(acc[1][j], a1, bb0, bb1);
        }
    }

    // ---- raw stats (pre-bias), then bias + fp16 pack ----
    uint32_t h2[2][2][8];   // [m][lo/hi][j]
#pragma unroll
    for (int j = 0; j < 8; j++) {
        int cA = col0 + 8 * j + 2 * t;
        float s0 = 0.f, s1 = 0.f, q0 = 0.f, q1 = 0.f;
#pragma unroll
        for (int m = 0; m < 2; m++) {
            const float* c = acc[m][j];
            s0 += c[0] + c[2];           s1 += c[1] + c[3];
            q0 += c[0] * c[0] + c[2] * c[2];
            q1 += c[1] * c[1] + c[3] * c[3];
        }
#pragma unroll
        for (int off = 4; off < 32; off <<= 1) {
            s0 += __shfl_xor_sync(0xffffffffu, s0, off);
            s1 += __shfl_xor_sync(0xffffffffu, s1, off);
            q0 += __shfl_xor_sync(0xffffffffu, q0, off);
            q1 += __shfl_xor_sync(0xffffffffu, q1, off);
        }
        if (lane < 4) {
            atomicAdd(&sSum[cA], s0); atomicAdd(&sSum[cA + 1], s1);
            atomicAdd(&sSq[cA], q0);  atomicAdd(&sSq[cA + 1], q1);
        }
        float bA = sBias[cA], bB = sBias[cA + 1];
#pragma unroll
        for (int m = 0; m < 2; m++) {
            const float* c = acc[m][j];
            half2 lo = __floats2half2_rn(c[0] + bA, c[1] + bB);
            half2 hi = __floats2half2_rn(c[2] + bA, c[3] + bB);
            h2[m][0][j] = *reinterpret_cast<uint32_t*>(&lo);
            h2[m][1][j] = *reinterpret_cast<uint32_t*>(&hi);
        }
    }

    __syncthreads();  // all As reads + smem stat adds done

    // ---- stage z tile into As via stmatrix ----
    {
        int jj = lane >> 3;
#pragma unroll
        for (int m = 0; m < 2; m++)
#pragma unroll
            for (int hh = 0; hh < 2; hh++) {
                int row_base = row0 + 16 * m + 8 * hh;
                uint32_t addr = As_b +
                    (uint32_t)(((row_base + r8) * SROW + col0 + jj * 8) * 2);
                stsm_x4(addr, h2[m][hh][0], h2[m][hh][1], h2[m][hh][2], h2[m][hh][3]);
                stsm_x4(addr + 64, h2[m][hh][4], h2[m][hh][5], h2[m][hh][6], h2[m][hh][7]);
            }
    }
    __syncthreads();

    if (tid < 128) {
        atomicAdd(&g_s[LAYER][tid], sSum[tid]);
        atomicAdd(&g_q[LAYER][tid], sSq[tid]);
    }

    half* Z = (LAYER == 0) ? g_z1 : g_z2;
#pragma unroll
    for (int i = 0; i < 8; i++) {
        int linear = tid + i * 256;
        int r = linear >> 4, c16 = linear & 15;
        long long e = e0 + r;
        if (e < E) {
            *reinterpret_cast<uint4*>(Z + e * 128 + c16 * 8) =
                *reinterpret_cast<const uint4*>(As + r * SROW + c16 * 8);
        }
    }
}

// Finalize BN stats from raw sums: mean = S/E + b, var = Q/E - (S/E)^2.
// Layer 0 additionally emits shp (fp16) for the folded layer-1 staging.
__global__ void k_finalize(const float* __restrict__ bias,
                           const float* __restrict__ gamma,
                           const float* __restrict__ beta,
                           int layer, int E) {
    int c = threadIdx.x;
    float b = bias[c];
    float invE = 1.0f / (float)E;
    float mp = g_s[layer][c] * invE;            // mean of raw z'
    float var = g_q[layer][c] * invE - mp * mp; // bias-invariant
    float mean = mp + b;
    float sc = gamma[c] * rsqrtf(var + 1e-5f);
    g_scale[layer][c] = sc;
    g_shift[layer][c] = fmaf(-mean, sc, beta[c]);
    if (layer == 0)
        g_shp_h[c] = __float2half_rn(beta[c] / sc - mean);
}

// Final: h2 = relu(BN2(z2)); out = h2@wc + bc. One warp per edge-row.
__global__ void k_out(const float* __restrict__ wc, const float* __restrict__ bc,
                      float* __restrict__ out, int E) {
    int lane = threadIdx.x & 31;
    int warpG = (blockIdx.x * blockDim.x + threadIdx.x) >> 5;
    int nW = (gridDim.x * blockDim.x) >> 5;
    int c0 = lane * 4;
    float sc[4], sh[4], w[4];
#pragma unroll
    for (int i = 0; i < 4; i++) {
        sc[i] = g_scale[1][c0 + i];
        sh[i] = g_shift[1][c0 + i];
        w[i]  = wc[c0 + i];
    }
    float b = bc[0];
    for (long long e = warpG; e < E; e += nW) {
        uint2 v = *reinterpret_cast<const uint2*>(g_z2 + e * 128 + c0);
        const half* zh = reinterpret_cast<const half*>(&v);
        float accv = 0.f;
#pragma unroll
        for (int i = 0; i < 4; i++) {
            float zf = __half2float(zh[i]);
            float h = fmaxf(fmaf(zf, sc[i], sh[i]), 0.f);
            accv = fmaf(h, w[i], accv);
        }
#pragma unroll
        for (int off = 16; off > 0; off >>= 1)
            accv += __shfl_xor_sync(0xffffffffu, accv, off);
        if (lane == 0) out[e] = accv + b;
    }
}

extern "C" void kernel_launch(void* const* d_in, const int* in_sizes, int n_in,
                              void* d_out, int out_size) {
    const float* x     = (const float*)d_in[0];
    const void*  edges = d_in[1];
    const float* w1 = (const float*)d_in[2];
    const float* b1 = (const float*)d_in[3];
    const float* g1 = (const float*)d_in[4];
    const float* be1 = (const float*)d_in[5];
    const float* w2 = (const float*)d_in[6];
    const float* b2 = (const float*)d_in[7];
    const float* g2 = (const float*)d_in[8];
    const float* be2 = (const float*)d_in[9];
    const float* wc = (const float*)d_in[10];
    const float* bc = (const float*)d_in[11];
    float* out = (float*)d_out;

    int E = in_sizes[1] / 2;
    int NB = (E + MT - 1) / MT;

    size_t smem = (size_t)(MT * SROW + 128 * SROW) * sizeof(half) + 3 * 128 * sizeof(float);
    cudaFuncSetAttribute(k_gemm<0>, cudaFuncAttributeMaxDynamicSharedMemorySize, (int)smem);
    cudaFuncSetAttribute(k_gemm<1>, cudaFuncAttributeMaxDynamicSharedMemorySize, (int)smem);

    k_prep<<<64, 256>>>(edges, w1);
    k_gemm<0><<<NB, 256, smem>>>(x, edges, b1, E);
    k_finalize<<<1, 128>>>(b1, g1, be1, 0, E);
    k_scalew<<<64, 256>>>(w2);
    k_gemm<1><<<NB, 256, smem>>>(x, edges, b2, E);
    k_finalize<<<1, 128>>>(b2, g2, be2, 1, E);
    k_out<<<2048, 256>>>(wc, bc, out, E);
}

// round 8
// speedup vs baseline: 1.7150x; 1.2451x over previous
#include <cuda_runtime.h>
#include <cuda_fp16.h>
#include <cstdint>

// ---------------------------------------------------------------------------
// CELP edge-MLP, round 8:
//  - x pre-converted to fp16 (gather does HMUL2, half the L2 traffic)
//  - raw z' storage (bias folded into BN shifts analytically)
//  - k_out: 2 rows/warp, uint4 loads
// ---------------------------------------------------------------------------

#define EMAX 1000000
#define NMAX 100000
#define MT 128          // rows (edges) per block tile
#define SROW 136        // smem row stride in halfs (272B, conflict-free)

static __device__ __align__(16) __half g_z1[(size_t)EMAX * 128];
static __device__ __align__(16) __half g_z2[(size_t)EMAX * 128];
static __device__ __align__(16) __half g_xh[(size_t)NMAX * 128];
static __device__ __align__(16) __half g_w1h[128 * 128];   // fp16 w1 [k][n]
static __device__ __align__(16) __half g_w2s[128 * 128];   // fp16 sc1⊙w2 [k][n]
static __device__ __align__(16) __half g_shp_h[128];       // fp16 raw-z shift, layer-1 stage
static __device__ float g_s[2][128];
static __device__ float g_q[2][128];
static __device__ float g_scale[2][128];
static __device__ float g_shift[2][128];
static __device__ int g_is64;

// x -> fp16
__global__ void k_prepx(const float* __restrict__ x, int nx) {
    int idx = (blockIdx.x * 256 + threadIdx.x) * 8;
    if (idx < nx) {
        float4 a = *reinterpret_cast<const float4*>(x + idx);
        float4 b = *reinterpret_cast<const float4*>(x + idx + 4);
        half2 h[4];
        h[0] = __floats2half2_rn(a.x, a.y);
        h[1] = __floats2half2_rn(a.z, a.w);
        h[2] = __floats2half2_rn(b.x, b.y);
        h[3] = __floats2half2_rn(b.z, b.w);
        *reinterpret_cast<uint4*>(g_xh + idx) = *reinterpret_cast<uint4*>(h);
    }
}

// fp16 w1, zero stats, edge dtype detect
__global__ void k_prepw(const void* edges, const float* __restrict__ w1) {
    int idx = blockIdx.x * 256 + threadIdx.x;   // 0..16383
    g_w1h[idx] = __float2half_rn(w1[idx]);
    if (blockIdx.x == 0) {
        int t = threadIdx.x;
        if (t < 128) {
            g_s[0][t] = 0.f; g_s[1][t] = 0.f;
            g_q[0][t] = 0.f; g_q[1][t] = 0.f;
        }
        if (t == 0) {
            const long long* e64 = (const long long*)edges;
            int is64 = 1;
            for (int i = 0; i < 8; i++) {
                long long v = e64[i];
                if (v < 0 || v >= (1LL << 31)) is64 = 0;
            }
            g_is64 = is64;
        }
    }
}

// w2' = diag(sc1) @ w2 in fp16 (after k_finalize layer 0)
__global__ void k_scalew(const float* __restrict__ w2) {
    int idx = blockIdx.x * 256 + threadIdx.x;   // 0..16383
    int k = idx >> 7;
    g_w2s[idx] = __float2half_rn(g_scale[0][k] * w2[idx]);
}

__device__ __forceinline__ void mma16816(float* c, const uint32_t* a,
                                         uint32_t b0, uint32_t b1) {
    asm volatile(
        "mma.sync.aligned.m16n8k16.row.col.f32.f16.f16.f32 "
        "{%0,%1,%2,%3}, {%4,%5,%6,%7}, {%8,%9}, {%0,%1,%2,%3};\n"
        : "+f"(c[0]), "+f"(c[1]), "+f"(c[2]), "+f"(c[3])
        : "r"(a[0]), "r"(a[1]), "r"(a[2]), "r"(a[3]), "r"(b0), "r"(b1));
}
__device__ __forceinline__ void ldsm_x4(uint32_t addr, uint32_t* r) {
    asm volatile("ldmatrix.sync.aligned.m8n8.x4.shared.b16 {%0,%1,%2,%3}, [%4];"
                 : "=r"(r[0]), "=r"(r[1]), "=r"(r[2]), "=r"(r[3]) : "r"(addr));
}
__device__ __forceinline__ void ldsm_x4_t(uint32_t addr, uint32_t* r) {
    asm volatile("ldmatrix.sync.aligned.m8n8.x4.trans.shared.b16 {%0,%1,%2,%3}, [%4];"
                 : "=r"(r[0]), "=r"(r[1]), "=r"(r[2]), "=r"(r[3]) : "r"(addr));
}
__device__ __forceinline__ void stsm_x4(uint32_t addr, uint32_t r0, uint32_t r1,
                                        uint32_t r2, uint32_t r3) {
    asm volatile("stmatrix.sync.aligned.m8n8.x4.shared.b16 [%0], {%1,%2,%3,%4};"
                 :: "r"(addr), "r"(r0), "r"(r1), "r"(r2), "r"(r3) : "memory");
}
#define CP_ASYNC16(dst, src) \
    asm volatile("cp.async.cg.shared.global [%0], [%1], 16;" :: "r"(dst), "l"(src))
#define CP_COMMIT() asm volatile("cp.async.commit_group;" ::: "memory")
#define CP_WAIT0()  asm volatile("cp.async.wait_group 0;" ::: "memory")

// LAYER 0: gather+hadamard(fp16) -> A, GEMM w1 -> raw stats, store z1' (raw)
// LAYER 1: load z1', +shp, relu -> A, GEMM w2' -> raw stats, store z2' (raw)
template <int LAYER>
__global__ __launch_bounds__(256, 2) void k_gemm(
    const void* __restrict__ edges_raw, int E) {
    extern __shared__ char smem_raw[];
    half* As = reinterpret_cast<half*>(smem_raw);
    half* Ws = As + MT * SROW;                       // W row-major [k][n], fp16
    float* sSum = reinterpret_cast<float*>(Ws + 128 * SROW);
    float* sSq  = sSum + 128;

    const int tid = threadIdx.x;
    const long long e0 = (long long)blockIdx.x * MT;
    const uint32_t As_b = (uint32_t)__cvta_generic_to_shared(As);
    const uint32_t Ws_b = (uint32_t)__cvta_generic_to_shared(Ws);

    // ---- stage fp16 W via cp.async ----
    {
        const half* WT = (LAYER == 0) ? g_w1h : g_w2s;
#pragma unroll
        for (int it = 0; it < 8; it++) {
            int idx = tid + it * 256;            // 0..2047
            int k = idx >> 4, n16 = idx & 15;
            uint32_t dst = Ws_b + (uint32_t)((k * SROW + n16 * 8) * 2);
            CP_ASYNC16(dst, WT + k * 128 + n16 * 8);
        }
        CP_COMMIT();
    }
    if (tid < 128) { sSum[tid] = 0.f; sSq[tid] = 0.f; }

    if (LAYER == 0) {
        // gather + hadamard (fp16 x). 2 threads per row (64 ch each).
        int r = tid >> 1, t2 = tid & 1;
        long long e = e0 + r;
        half* dst = As + r * SROW + t2 * 64;
        if (e < E) {
            long long ia, ib;
            if (g_is64) {
                const long long* e64 = (const long long*)edges_raw;
                ia = e64[e]; ib = e64[(long long)E + e];
            } else {
                const int* e32 = (const int*)edges_raw;
                ia = e32[e]; ib = e32[(long long)E + e];
            }
            const uint4* xa = reinterpret_cast<const uint4*>(g_xh + ia * 128) + t2 * 8;
            const uint4* xb = reinterpret_cast<const uint4*>(g_xh + ib * 128) + t2 * 8;
#pragma unroll
            for (int i = 0; i < 8; i++) {
                uint4 va = xa[i], vb = xb[i];
                half2* pa = reinterpret_cast<half2*>(&va);
                half2* pb = reinterpret_cast<half2*>(&vb);
                pa[0] = __hmul2(pa[0], pb[0]);
                pa[1] = __hmul2(pa[1], pb[1]);
                pa[2] = __hmul2(pa[2], pb[2]);
                pa[3] = __hmul2(pa[3], pb[3]);
                *reinterpret_cast<uint4*>(dst + i * 8) = va;
            }
        } else {
            uint4 z = make_uint4(0u, 0u, 0u, 0u);
#pragma unroll
            for (int i = 0; i < 8; i++)
                *reinterpret_cast<uint4*>(dst + i * 8) = z;
        }
        CP_WAIT0();
        __syncthreads();
    } else {
        // h1 = relu(z1' + shp), shp = beta/sc - mp (raw-z form)
        const __half2* shp2 = reinterpret_cast<const __half2*>(g_shp_h) + (tid & 15) * 4;
        half2 sh0 = shp2[0], sh1 = shp2[1], sh2 = shp2[2], sh3 = shp2[3];
        half2 zz = __floats2half2_rn(0.f, 0.f);
#pragma unroll
        for (int i = 0; i < 8; i++) {
            int linear = tid + i * 256;          // 0..2047
            int r = linear >> 4, c16 = linear & 15;
            long long e = e0 + r;
            uint4 outv = make_uint4(0u, 0u, 0u, 0u);
            if (e < E) {
                uint4 v = *reinterpret_cast<const uint4*>(g_z1 + e * 128 + c16 * 8);
                half2* p = reinterpret_cast<half2*>(&v);
                p[0] = __hmax2(__hadd2(p[0], sh0), zz);
                p[1] = __hmax2(__hadd2(p[1], sh1), zz);
                p[2] = __hmax2(__hadd2(p[2], sh2), zz);
                p[3] = __hmax2(__hadd2(p[3], sh3), zz);
                outv = v;
            }
            *reinterpret_cast<uint4*>(As + r * SROW + c16 * 8) = outv;
        }
        CP_WAIT0();
        __syncthreads();
    }

    // ---- GEMM: 128x128x128, 8 warps, warp tile 32x64, LDSM ----
    const int lane = tid & 31, warp = tid >> 5;
    const int t = lane & 3;
    const int wm = warp & 3, wn = warp >> 2;
    const int row0 = wm * 32, col0 = wn * 64;

    const int b3 = (lane >> 3) & 1, b4 = (lane >> 4) & 1, r8 = lane & 7;
    uint32_t a_off = As_b + (uint32_t)(((row0 + 8 * b3 + r8) * SROW + 8 * b4) * 2);
    uint32_t b_off = Ws_b + (uint32_t)(((8 * b3 + r8) * SROW + col0 + 8 * b4) * 2);

    float acc[2][8][4];
#pragma unroll
    for (int m = 0; m < 2; m++)
#pragma unroll
        for (int j = 0; j < 8; j++)
#pragma unroll
            for (int q = 0; q < 4; q++) acc[m][j][q] = 0.f;

#pragma unroll
    for (int kk = 0; kk < 128; kk += 16) {
        uint32_t a0[4], a1[4];
        ldsm_x4(a_off + kk * 2, a0);
        ldsm_x4(a_off + (16 * SROW + kk) * 2, a1);
        uint32_t bf[4][4];
#pragma unroll
        for (int p = 0; p < 4; p++)
            ldsm_x4_t(b_off + (kk * SROW + 16 * p) * 2, bf[p]);
#pragma unroll
        for (int j = 0; j < 8; j++) {
            uint32_t bb0 = bf[j >> 1][(j & 1) * 2];
            uint32_t bb1 = bf[j >> 1][(j & 1) * 2 + 1];
            mma16816(acc[0][j], a0, bb0, bb1);
            mma16816(acc[1][j], a1, bb0, bb1);
        }
    }

    // ---- raw stats + fp16 pack (no bias anywhere) ----
    uint32_t h2[2][2][8];   // [m][lo/hi][j]
#pragma unroll
    for (int j = 0; j < 8; j++) {
        int cA = col0 + 8 * j + 2 * t;
        float s0 = 0.f, s1 = 0.f, q0 = 0.f, q1 = 0.f;
#pragma unroll
        for (int m = 0; m < 2; m++) {
            const float* c = acc[m][j];
            s0 += c[0] + c[2];           s1 += c[1] + c[3];
            q0 += c[0] * c[0] + c[2] * c[2];
            q1 += c[1] * c[1] + c[3] * c[3];
            half2 lo = __floats2half2_rn(c[0], c[1]);
            half2 hi = __floats2half2_rn(c[2], c[3]);
            h2[m][0][j] = *reinterpret_cast<uint32_t*>(&lo);
            h2[m][1][j] = *reinterpret_cast<uint32_t*>(&hi);
        }
#pragma unroll
        for (int off = 4; off < 32; off <<= 1) {
            s0 += __shfl_xor_sync(0xffffffffu, s0, off);
            s1 += __shfl_xor_sync(0xffffffffu, s1, off);
            q0 += __shfl_xor_sync(0xffffffffu, q0, off);
            q1 += __shfl_xor_sync(0xffffffffu, q1, off);
        }
        if (lane < 4) {
            atomicAdd(&sSum[cA], s0); atomicAdd(&sSum[cA + 1], s1);
            atomicAdd(&sSq[cA], q0);  atomicAdd(&sSq[cA + 1], q1);
        }
    }

    __syncthreads();

    // ---- stage z' tile into As via stmatrix ----
    {
        int jj = lane >> 3;
#pragma unroll
        for (int m = 0; m < 2; m++)
#pragma unroll
            for (int hh = 0; hh < 2; hh++) {
                int row_base = row0 + 16 * m + 8 * hh;
                uint32_t addr = As_b +
                    (uint32_t)(((row_base + r8) * SROW + col0 + jj * 8) * 2);
                stsm_x4(addr, h2[m][hh][0], h2[m][hh][1], h2[m][hh][2], h2[m][hh][3]);
                stsm_x4(addr + 64, h2[m][hh][4], h2[m][hh][5], h2[m][hh][6], h2[m][hh][7]);
            }
    }
    __syncthreads();

    if (tid < 128) {
        atomicAdd(&g_s[LAYER][tid], sSum[tid]);
        atomicAdd(&g_q[LAYER][tid], sSq[tid]);
    }

    half* Z = (LAYER == 0) ? g_z1 : g_z2;
#pragma unroll
    for (int i = 0; i < 8; i++) {
        int linear = tid + i * 256;
        int r = linear >> 4, c16 = linear & 15;
        long long e = e0 + r;
        if (e < E) {
            *reinterpret_cast<uint4*>(Z + e * 128 + c16 * 8) =
                *reinterpret_cast<const uint4*>(As + r * SROW + c16 * 8);
        }
    }
}

// Finalize BN stats from raw sums (raw-z formulation; bias folded analytically).
__global__ void k_finalize(const float* __restrict__ gamma,
                           const float* __restrict__ beta,
                           int layer, int E) {
    int c = threadIdx.x;
    float invE = 1.0f / (float)E;
    float mp = g_s[layer][c] * invE;            // mean of raw z'
    float var = g_q[layer][c] * invE - mp * mp; // bias-invariant
    float sc = gamma[c] * rsqrtf(var + 1e-5f);
    g_scale[layer][c] = sc;
    g_shift[layer][c] = fmaf(-mp, sc, beta[c]); // raw-z shift
    if (layer == 0)
        g_shp_h[c] = __float2half_rn(beta[c] / sc - mp);
}

// Final: h2 = relu(sc2*z2' + sh2'); out = h2@wc + bc. 2 rows per warp, uint4.
__global__ void k_out(const float* __restrict__ wc, const float* __restrict__ bc,
                      float* __restrict__ out, int E) {
    int lane = threadIdx.x & 31;
    int rsel = lane >> 4, l16 = lane & 15;
    int warpG = (blockIdx.x * blockDim.x + threadIdx.x) >> 5;
    int nW = (gridDim.x * blockDim.x) >> 5;
    int c0 = l16 * 8;
    float sc[8], sh[8], w[8];
#pragma unroll
    for (int i = 0; i < 8; i++) {
        sc[i] = g_scale[1][c0 + i];
        sh[i] = g_shift[1][c0 + i];
        w[i]  = wc[c0 + i];
    }
    float b = bc[0];
    for (long long eb = (long long)warpG * 2; eb < E; eb += (long long)nW * 2) {
        long long e = eb + rsel;
        float accv = 0.f;
        if (e < E) {
            uint4 v = *reinterpret_cast<const uint4*>(g_z2 + e * 128 + c0);
            const half* zh = reinterpret_cast<const half*>(&v);
#pragma unroll
            for (int i = 0; i < 8; i++) {
                float zf = __half2float(zh[i]);
                float h = fmaxf(fmaf(zf, sc[i], sh[i]), 0.f);
                accv = fmaf(h, w[i], accv);
            }
        }
#pragma unroll
        for (int off = 8; off > 0; off >>= 1)
            accv += __shfl_xor_sync(0xffffffffu, accv, off);
        if (l16 == 0 && e < E) out[e] = accv + b;
    }
}

extern "C" void kernel_launch(void* const* d_in, const int* in_sizes, int n_in,
                              void* d_out, int out_size) {
    const float* x     = (const float*)d_in[0];
    const void*  edges = d_in[1];
    const float* w1 = (const float*)d_in[2];
    const float* g1 = (const float*)d_in[4];
    const float* be1 = (const float*)d_in[5];
    const float* w2 = (const float*)d_in[6];
    const float* g2 = (const float*)d_in[8];
    const float* be2 = (const float*)d_in[9];
    const float* wc = (const float*)d_in[10];
    const float* bc = (const float*)d_in[11];
    float* out = (float*)d_out;

    int E = in_sizes[1] / 2;
    int NB = (E + MT - 1) / MT;
    int nx = in_sizes[0];

    size_t smem = (size_t)(MT * SROW + 128 * SROW) * sizeof(half) + 2 * 128 * sizeof(float);
    cudaFuncSetAttribute(k_gemm<0>, cudaFuncAttributeMaxDynamicSharedMemorySize, (int)smem);
    cudaFuncSetAttribute(k_gemm<1>, cudaFuncAttributeMaxDynamicSharedMemorySize, (int)smem);

    k_prepx<<<(nx / 8 + 255) / 256, 256>>>(x, nx);
    k_prepw<<<64, 256>>>(edges, w1);
    k_gemm<0><<<NB, 256, smem>>>(edges, E);
    k_finalize<<<1, 128>>>(g1, be1, 0, E);
    k_scalew<<<64, 256>>>(w2);
    k_gemm<1><<<NB, 256, smem>>>(edges, E);
    k_finalize<<<1, 128>>>(g2, be2, 1, E);
    k_out<<<2048, 256>>>(wc, bc, out, E);
}